// round 1
// baseline (speedup 1.0000x reference)
#include <cuda_runtime.h>

// Problem constants (fixed by the reference setup)
#define LSEQ   768
#define BATCH  2
#define N_MSA  4
#define DM     128
#define NREL   63   // 2*MAX_LEN - 1

// Scratch tables (device globals — no allocation allowed)
__device__ float g_Ptab[5][DM];   // e[t] @ W_proj[:64, :]
__device__ float g_Qtab[5][DM];   // e[t] @ W_proj[64:, :]
__device__ float g_R[NREL][DM];   // W_pos[r] + b_proj + b_pos

// ---------------------------------------------------------------------------
// Table setup: 68 blocks x 128 threads. Blocks 0..4 -> Ptab/Qtab row t,
// blocks 5..67 -> R row (blockIdx-5). Tiny; runs in a few microseconds.
// ---------------------------------------------------------------------------
__global__ void setup_kernel(const float* __restrict__ emb,
                             const float* __restrict__ W_proj,
                             const float* __restrict__ b_proj,
                             const float* __restrict__ W_pos,
                             const float* __restrict__ b_pos) {
    int d = threadIdx.x;          // 0..127
    int task = blockIdx.x;
    if (task < 5) {
        int t = task;
        float pt = 0.f, qt = 0.f;
        if (t != 0) {             // token 0 is masked to zero (emb[0]==0 too)
            #pragma unroll 16
            for (int k = 0; k < 64; k++) {
                float ek = emb[t * 64 + k];
                pt = fmaf(ek, W_proj[k * DM + d], pt);
                qt = fmaf(ek, W_proj[(64 + k) * DM + d], qt);
            }
        }
        g_Ptab[t][d] = pt;
        g_Qtab[t][d] = qt;
    } else {
        int r = task - 5;
        g_R[r][d] = W_pos[r * DM + d] + b_proj[d] + b_pos[d];
    }
}

// ---------------------------------------------------------------------------
// Main kernel: one block per (b, i). Writes 768*128 fp32 = 393 KB, coalesced
// float4 streaming stores. Per-element work: 2x LDS.128 + 4 FADD + STG.128.
// ---------------------------------------------------------------------------
__global__ __launch_bounds__(256) void pair_kernel(const int* __restrict__ msa,
                                                   float* __restrict__ out) {
    __shared__ int    s_seq[LSEQ];
    __shared__ float4 s_R[NREL * 32];   // R rows as float4  (32256 B)
    __shared__ float4 s_CT[5 * 32];     // Ptab[si] + Qtab[t] (2560 B)

    int bx  = blockIdx.x;               // b*LSEQ + i
    int b   = bx / LSEQ;
    int i   = bx - b * LSEQ;
    int tid = threadIdx.x;

    // Load this batch's sequence (row 0 of the MSA) into shared
    const int* seq = msa + (size_t)b * N_MSA * LSEQ;
    for (int k = tid; k < LSEQ; k += 256) s_seq[k] = seq[k];

    // Load R table into shared as float4
    const float4* gR4 = (const float4*)g_R;
    for (int k = tid; k < NREL * 32; k += 256) s_R[k] = gR4[k];
    __syncthreads();

    int si   = s_seq[i];
    int lane = tid & 31;

    // Build the fused per-block table CT[t][d] = Ptab[si][d] + Qtab[t][d]
    if (tid < 5 * 32) {
        int t = tid >> 5;
        float4 p = ((const float4*)g_Ptab)[si * 32 + lane];
        float4 q = ((const float4*)g_Qtab)[t * 32 + lane];
        s_CT[tid] = make_float4(p.x + q.x, p.y + q.y, p.z + q.z, p.w + q.w);
    }
    __syncthreads();

    // Each warp handles rows j = warp, warp+8, ... ; lanes cover d (4 floats each)
    int warp = tid >> 5;
    float4* outp = (float4*)out + (size_t)bx * LSEQ * 32;

    for (int j = warp; j < LSEQ; j += 8) {
        int sj  = s_seq[j];                              // uniform across warp
        int rel = min(max(i - j, -31), 31) + 31;          // uniform across warp
        float4 c = s_CT[sj * 32 + lane];
        float4 r = s_R[rel * 32 + lane];
        float4 v = make_float4(c.x + r.x, c.y + r.y, c.z + r.z, c.w + r.w);
        __stcs(&outp[(size_t)j * 32 + lane], v);          // streaming store
    }
}

extern "C" void kernel_launch(void* const* d_in, const int* in_sizes, int n_in,
                              void* d_out, int out_size) {
    const int*   msa    = (const int*)  d_in[0];  // msa_tokens (B, N_MSA, L) int32
    const float* emb    = (const float*)d_in[1];  // (5, 64)
    const float* W_proj = (const float*)d_in[2];  // (128, 128)
    const float* b_proj = (const float*)d_in[3];  // (128,)
    const float* W_pos  = (const float*)d_in[4];  // (63, 128)
    const float* b_pos  = (const float*)d_in[5];  // (128,)
    float* out = (float*)d_out;                   // (B, L, L, 128) fp32

    setup_kernel<<<5 + NREL, DM>>>(emb, W_proj, b_proj, W_pos, b_pos);
    pair_kernel<<<BATCH * LSEQ, 256>>>(msa, out);
}